// round 1
// baseline (speedup 1.0000x reference)
#include <cuda_runtime.h>

// Problem constants
#define DIMV   1024
#define BATCHV 2
#define SEQV   2048
#define MROWS  (BATCHV * SEQV)   // 4096

// Scratch (allocation-free rule: __device__ globals)
__device__ float g_q[BATCHV * SEQV * DIMV];
__device__ float g_k[BATCHV * SEQV * DIMV];
__device__ float g_v[BATCHV * SEQV * DIMV];
__device__ float g_s[BATCHV * SEQV * SEQV];
__device__ float g_o[BATCHV * SEQV * DIMV];

// ----------------------------------------------------------------------------
// SGEMM: C = A @ op(B) + bias,  128x128 block tile, BK=16, 256 threads, 8x8/thread
//   BTRANS = true : B stored [N, K] row-major (compute A @ B^T)   -- "NT"
//   BTRANS = false: B stored [K, N] row-major (compute A @ B)     -- "NN"
// A: [M, K] row-major. C: [M, N] row-major. All dims multiples of 128/16 here.
// Batched via blockIdx.z with element strides sA/sB/sC.
// ----------------------------------------------------------------------------
template <bool BTRANS>
__global__ __launch_bounds__(256, 2)
void sgemm_kernel(const float* __restrict__ Ag, const float* __restrict__ Bg,
                  const float* __restrict__ bias, float* __restrict__ Cg,
                  int M, int N, int K,
                  long long sA, long long sB, long long sC)
{
    const int bz = blockIdx.z;
    const float* A = Ag + (long long)bz * sA;
    const float* B = Bg + (long long)bz * sB;
    float*       C = Cg + (long long)bz * sC;

    __shared__ float As[16][128];
    __shared__ float Bs[16][128];

    const int tid = threadIdx.x;
    const int tx  = tid & 15;    // 0..15 -> col group
    const int ty  = tid >> 4;    // 0..15 -> row group

    const int m0 = blockIdx.y * 128;
    const int n0 = blockIdx.x * 128;

    float acc[8][8];
#pragma unroll
    for (int i = 0; i < 8; i++)
#pragma unroll
        for (int j = 0; j < 8; j++) acc[i][j] = 0.0f;

    for (int k0 = 0; k0 < K; k0 += 16) {
        // ---- load A tile [128 rows x 16 k] -> As[k][m] (transposed in smem)
#pragma unroll
        for (int l = 0; l < 2; l++) {
            int p   = tid + l * 256;      // 0..511 float4 slots
            int row = p >> 2;             // 0..127
            int c4  = (p & 3) * 4;        // 0,4,8,12
            float4 va = *reinterpret_cast<const float4*>(
                &A[(long long)(m0 + row) * K + k0 + c4]);
            As[c4 + 0][row] = va.x;
            As[c4 + 1][row] = va.y;
            As[c4 + 2][row] = va.z;
            As[c4 + 3][row] = va.w;
        }
        // ---- load B tile -> Bs[k][n]
        if (BTRANS) {
#pragma unroll
            for (int l = 0; l < 2; l++) {
                int p   = tid + l * 256;
                int row = p >> 2;          // 0..127 (n index)
                int c4  = (p & 3) * 4;     // k offset
                float4 vb = *reinterpret_cast<const float4*>(
                    &B[(long long)(n0 + row) * K + k0 + c4]);
                Bs[c4 + 0][row] = vb.x;
                Bs[c4 + 1][row] = vb.y;
                Bs[c4 + 2][row] = vb.z;
                Bs[c4 + 3][row] = vb.w;
            }
        } else {
#pragma unroll
            for (int l = 0; l < 2; l++) {
                int p   = tid + l * 256;
                int row = p >> 5;          // 0..15 (k index)
                int c4  = (p & 31) * 4;    // 0..124 (n offset)
                float4 vb = *reinterpret_cast<const float4*>(
                    &B[(long long)(k0 + row) * N + n0 + c4]);
                *reinterpret_cast<float4*>(&Bs[row][c4]) = vb;
            }
        }
        __syncthreads();

        // ---- compute
#pragma unroll
        for (int kk = 0; kk < 16; kk++) {
            float ra[8], rb[8];
            *reinterpret_cast<float4*>(&ra[0]) =
                *reinterpret_cast<const float4*>(&As[kk][ty * 8]);
            *reinterpret_cast<float4*>(&ra[4]) =
                *reinterpret_cast<const float4*>(&As[kk][ty * 8 + 4]);
            *reinterpret_cast<float4*>(&rb[0]) =
                *reinterpret_cast<const float4*>(&Bs[kk][tx * 8]);
            *reinterpret_cast<float4*>(&rb[4]) =
                *reinterpret_cast<const float4*>(&Bs[kk][tx * 8 + 4]);
#pragma unroll
            for (int i = 0; i < 8; i++)
#pragma unroll
                for (int j = 0; j < 8; j++)
                    acc[i][j] = fmaf(ra[i], rb[j], acc[i][j]);
        }
        __syncthreads();
    }

    // ---- epilogue (optional bias along N)
#pragma unroll
    for (int i = 0; i < 8; i++) {
        long long m = m0 + ty * 8 + i;
#pragma unroll
        for (int j = 0; j < 8; j += 4) {
            int n = n0 + tx * 8 + j;
            float4 v;
            v.x = acc[i][j + 0];
            v.y = acc[i][j + 1];
            v.z = acc[i][j + 2];
            v.w = acc[i][j + 3];
            if (bias) {
                v.x += bias[n + 0];
                v.y += bias[n + 1];
                v.z += bias[n + 2];
                v.w += bias[n + 3];
            }
            *reinterpret_cast<float4*>(&C[m * N + n]) = v;
        }
    }
}

// ----------------------------------------------------------------------------
// Fused theta + row softmax, in place on S[rows][SEQV].
// theta = 0.5 + 0.2*sigmoid(x) + 0.15*tanh(x) + 0.1*relu(x); softmax over row.
// One block (256 threads) per row; each thread owns 8 strided columns.
// ----------------------------------------------------------------------------
__global__ __launch_bounds__(256)
void theta_softmax_kernel(float* __restrict__ S)
{
    float* p = S + (long long)blockIdx.x * SEQV;
    const int tid  = threadIdx.x;
    const int lane = tid & 31;
    const int wid  = tid >> 5;

    __shared__ float red[8];

    float th[8];
    float mx = -1e30f;
#pragma unroll
    for (int j = 0; j < 8; j++) {
        float x = p[tid + j * 256];
        float sg = 1.0f / (1.0f + __expf(-x));
        float t;
        asm("tanh.approx.f32 %0, %1;" : "=f"(t) : "f"(x));
        float r = fmaxf(x, 0.0f);
        float v = 0.5f + 0.2f * sg + 0.15f * t + 0.1f * r;
        th[j] = v;
        mx = fmaxf(mx, v);
    }
    // block max
#pragma unroll
    for (int o = 16; o > 0; o >>= 1)
        mx = fmaxf(mx, __shfl_xor_sync(0xFFFFFFFFu, mx, o));
    if (lane == 0) red[wid] = mx;
    __syncthreads();
    mx = red[0];
#pragma unroll
    for (int w = 1; w < 8; w++) mx = fmaxf(mx, red[w]);
    __syncthreads();

    // exp + sum
    float sum = 0.0f;
#pragma unroll
    for (int j = 0; j < 8; j++) {
        float e = __expf(th[j] - mx);
        th[j] = e;
        sum += e;
    }
#pragma unroll
    for (int o = 16; o > 0; o >>= 1)
        sum += __shfl_xor_sync(0xFFFFFFFFu, sum, o);
    if (lane == 0) red[wid] = sum;
    __syncthreads();
    sum = red[0];
#pragma unroll
    for (int w = 1; w < 8; w++) sum += red[w];

    float inv = 1.0f / sum;
#pragma unroll
    for (int j = 0; j < 8; j++)
        p[tid + j * 256] = th[j] * inv;
}

// ----------------------------------------------------------------------------
// Launch
// Inputs (metadata order): x, Wq, bq, Wk, bk, Wv, bv, Wo, bo
// ----------------------------------------------------------------------------
extern "C" void kernel_launch(void* const* d_in, const int* in_sizes, int n_in,
                              void* d_out, int out_size)
{
    const float* x  = (const float*)d_in[0];
    const float* Wq = (const float*)d_in[1];
    const float* bq = (const float*)d_in[2];
    const float* Wk = (const float*)d_in[3];
    const float* bk = (const float*)d_in[4];
    const float* Wv = (const float*)d_in[5];
    const float* bv = (const float*)d_in[6];
    const float* Wo = (const float*)d_in[7];
    const float* bo = (const float*)d_in[8];
    float* out = (float*)d_out;

    void *pq, *pk, *pv, *ps, *po;
    cudaGetSymbolAddress(&pq, g_q);
    cudaGetSymbolAddress(&pk, g_k);
    cudaGetSymbolAddress(&pv, g_v);
    cudaGetSymbolAddress(&ps, g_s);
    cudaGetSymbolAddress(&po, g_o);
    float* q = (float*)pq;
    float* k = (float*)pk;
    float* v = (float*)pv;
    float* s = (float*)ps;
    float* o = (float*)po;

    const long long QKV_STRIDE = (long long)SEQV * DIMV;   // per-batch q/k/v/o stride
    const long long S_STRIDE   = (long long)SEQV * SEQV;   // per-batch scores stride

    dim3 blk(256);

    // 1) Projections: [4096,1024] = x @ W^T + b  (NT)
    {
        dim3 grid(DIMV / 128, MROWS / 128, 1);
        sgemm_kernel<true><<<grid, blk>>>(x, Wq, bq, q, MROWS, DIMV, DIMV, 0, 0, 0);
        sgemm_kernel<true><<<grid, blk>>>(x, Wk, bk, k, MROWS, DIMV, DIMV, 0, 0, 0);
        sgemm_kernel<true><<<grid, blk>>>(x, Wv, bv, v, MROWS, DIMV, DIMV, 0, 0, 0);
    }

    // 2) Scores: S[b] = Q[b] @ K[b]^T  (NT, batched)
    {
        dim3 grid(SEQV / 128, SEQV / 128, BATCHV);
        sgemm_kernel<true><<<grid, blk>>>(q, k, nullptr, s, SEQV, SEQV, DIMV,
                                          QKV_STRIDE, QKV_STRIDE, S_STRIDE);
    }

    // 3) theta + softmax in place
    theta_softmax_kernel<<<BATCHV * SEQV, blk>>>(s);

    // 4) O[b] = P[b] @ V[b]  (NN, batched)
    {
        dim3 grid(DIMV / 128, SEQV / 128, BATCHV);
        sgemm_kernel<false><<<grid, blk>>>(s, v, nullptr, o, SEQV, DIMV, SEQV,
                                           S_STRIDE, QKV_STRIDE, QKV_STRIDE);
    }

    // 5) Output projection: out = O @ Wo^T + bo  (NT)
    {
        dim3 grid(DIMV / 128, MROWS / 128, 1);
        sgemm_kernel<true><<<grid, blk>>>(o, Wo, bo, out, MROWS, DIMV, DIMV, 0, 0, 0);
    }
}

// round 3
// speedup vs baseline: 1.7251x; 1.7251x over previous
#include <cuda_runtime.h>
#include <cstdint>

// ---------------- problem constants ----------------
#define SEQ    2048
#define DIMN   1024
#define BATCH  2
#define MR     4096            // BATCH*SEQ

// ---------------- GEMM tiling ----------------
#define BM 128
#define BN 128
#define BK 32
#define NTHREADS 256

#define TILEB  (BM * BK * 4)           // 16384 B per operand tile
#define STAGE  (4 * TILEB)             // Ah, Al, Bh, Bl = 65536 B
#define SMEM_BYTES (2 * STAGE)         // 131072 B

// ---------------- scratch (__device__ globals; no allocs allowed) ----------------
static __device__ float g_xh[MR * DIMN],  g_xl[MR * DIMN];
static __device__ float g_wh[4][DIMN * DIMN], g_wl[4][DIMN * DIMN]; // q,k,v,o
static __device__ float g_qh[MR * DIMN],  g_ql[MR * DIMN];
static __device__ float g_kh[MR * DIMN],  g_kl[MR * DIMN];
static __device__ float g_vTh[MR * DIMN], g_vTl[MR * DIMN];         // [B][D][S]
static __device__ float g_s[BATCH * SEQ * SEQ];
static __device__ float g_ph[BATCH * SEQ * SEQ], g_pl[BATCH * SEQ * SEQ];
static __device__ float g_oh[MR * DIMN],  g_ol[MR * DIMN];

// ---------------- helpers ----------------
__device__ __forceinline__ uint32_t smem_u32(const void* p) {
    uint32_t a;
    asm("{ .reg .u64 t; cvta.to.shared.u64 t, %1; cvt.u32.u64 %0, t; }"
        : "=r"(a) : "l"(p));
    return a;
}

__device__ __forceinline__ float f2tf32(float x) {
    uint32_t u;
    asm("cvt.rna.tf32.f32 %0, %1;" : "=r"(u) : "f"(x));
    return __uint_as_float(u);
}

__device__ __forceinline__ void cp16(uint32_t saddr, const float* g) {
    asm volatile("cp.async.cg.shared.global [%0], [%1], 16;"
                 :: "r"(saddr), "l"(g) : "memory");
}

__device__ __forceinline__ void ldsm4(uint32_t* r, uint32_t addr) {
    asm volatile("ldmatrix.sync.aligned.m8n8.x4.shared.b16 {%0,%1,%2,%3}, [%4];"
                 : "=r"(r[0]), "=r"(r[1]), "=r"(r[2]), "=r"(r[3])
                 : "r"(addr));
}

__device__ __forceinline__ void mma_tf32(float* d, const uint32_t* a,
                                         uint32_t b0, uint32_t b1) {
    asm volatile(
        "mma.sync.aligned.m16n8k8.row.col.f32.tf32.tf32.f32 "
        "{%0,%1,%2,%3}, {%4,%5,%6,%7}, {%8,%9}, {%0,%1,%2,%3};"
        : "+f"(d[0]), "+f"(d[1]), "+f"(d[2]), "+f"(d[3])
        : "r"(a[0]), "r"(a[1]), "r"(a[2]), "r"(a[3]), "r"(b0), "r"(b1));
}

__device__ __forceinline__ uint32_t sw128(uint32_t x) {
    return x ^ ((x >> 3) & 0x70);   // 128B-row xor swizzle
}

// ----------------------------------------------------------------------------
// tf32x3 GEMM via mma.sync:  C[M,N] = (Ah+Al)[M,K] @ (Bh+Bl)[N,K]^T
// EPI: 0 = plain fp32 store (+optional bias)        (QK scores, final output)
//      1 = split store hi/lo (+optional bias)       (q/k projections, PV out)
//      2 = split store TRANSPOSED [b][n][t] (+bias) (v projection -> v^T)
// ----------------------------------------------------------------------------
template <int EPI>
__global__ void __launch_bounds__(NTHREADS, 1)
gemm_x3(const float* __restrict__ Ah, const float* __restrict__ Al,
        const float* __restrict__ Bh, const float* __restrict__ Bl,
        const float* __restrict__ bias,
        float* __restrict__ C0, float* __restrict__ C1,
        int M, int N, int K,
        long long sA, long long sB, long long sC)
{
    extern __shared__ char dsmem[];
    const uint32_t sbase = smem_u32(dsmem);

    const int tid  = threadIdx.x;
    const int lane = tid & 31;
    const int wid  = tid >> 5;
    const int wm   = wid >> 2;        // 0..1 (m warp row)
    const int wn   = wid & 3;         // 0..3 (n warp col)

    const int m0 = blockIdx.y * BM;
    const int n0 = blockIdx.x * BN;
    const int bz = blockIdx.z;

    const float* pAh = Ah + (long long)bz * sA;
    const float* pAl = Al + (long long)bz * sA;
    const float* pBh = Bh + (long long)bz * sB;
    const float* pBl = Bl + (long long)bz * sB;

    // ---- cp.async slots: each thread copies 4 x 16B chunks per operand tile
    uint32_t g_sw[4];    // swizzled smem offset within a tile
    int      a_off[4];   // gmem float offset for A rows
    int      b_off[4];   // gmem float offset for B rows
#pragma unroll
    for (int i = 0; i < 4; i++) {
        int c   = tid + i * NTHREADS;        // 0..1023
        int row = c >> 3;                    // 0..127
        int ch  = c & 7;                     // 16B chunk in 128B row
        g_sw[i]  = sw128((uint32_t)(row * 128 + ch * 16));
        a_off[i] = (m0 + row) * K + ch * 4;
        b_off[i] = (n0 + row) * K + ch * 4;
    }

    auto load_tile = [&](int kt, int s) {
        const int k0 = kt * BK;
        const uint32_t st = sbase + (uint32_t)s * STAGE;
#pragma unroll
        for (int i = 0; i < 4; i++) {
            cp16(st + g_sw[i],             pAh + a_off[i] + k0);
            cp16(st + TILEB + g_sw[i],     pAl + a_off[i] + k0);
            cp16(st + 2 * TILEB + g_sw[i], pBh + b_off[i] + k0);
            cp16(st + 3 * TILEB + g_sw[i], pBl + b_off[i] + k0);
        }
        asm volatile("cp.async.commit_group;" ::: "memory");
    };

    // ---- ldmatrix address components (lane-dependent, loop-invariant)
    const int piece = lane >> 3;   // which 8x8 matrix this lane addresses
    const int pr    = lane & 7;    // row within matrix

    // A x4 tile (m16 x k8) at (mt, ks):
    //   matrices: {m0-7,k0-3},{m8-15,k0-3},{m0-7,k4-7},{m8-15,k4-7}
    int a_row[4], a_chunk[4];
#pragma unroll
    for (int mt = 0; mt < 4; mt++)
        a_row[mt] = (wm * 64 + mt * 16 + ((piece & 1) << 3) + pr) * 128;
#pragma unroll
    for (int ks = 0; ks < 4; ks++)
        a_chunk[ks] = (ks * 2 + (piece >> 1)) * 16;

    // B x4 tile (n16 x k8) at (nt2, ks):
    //   matrices: {n0-7,k0-3},{n0-7,k4-7},{n8-15,k0-3},{n8-15,k4-7}
    int b_row[2], b_chunk[4];
#pragma unroll
    for (int nt2 = 0; nt2 < 2; nt2++)
        b_row[nt2] = (wn * 32 + nt2 * 16 + ((piece >> 1) << 3) + pr) * 128;
#pragma unroll
    for (int ks = 0; ks < 4; ks++)
        b_chunk[ks] = (ks * 2 + (piece & 1)) * 16;

    float acc[4][4][4];
#pragma unroll
    for (int i = 0; i < 4; i++)
#pragma unroll
        for (int j = 0; j < 4; j++)
#pragma unroll
            for (int r = 0; r < 4; r++) acc[i][j][r] = 0.0f;

    const int KT = K / BK;
    load_tile(0, 0);

    for (int kt = 0; kt < KT; kt++) {
        const int s = kt & 1;
        asm volatile("cp.async.wait_group 0;" ::: "memory");
        __syncthreads();
        if (kt + 1 < KT) load_tile(kt + 1, s ^ 1);

        const uint32_t sAh = sbase + (uint32_t)s * STAGE;
        const uint32_t sAl = sAh + TILEB;
        const uint32_t sBh = sAh + 2 * TILEB;
        const uint32_t sBl = sAh + 3 * TILEB;

#pragma unroll
        for (int ks = 0; ks < 4; ks++) {
            uint32_t fAh[4][4], fAl[4][4];
#pragma unroll
            for (int mt = 0; mt < 4; mt++) {
                uint32_t so = sw128((uint32_t)(a_row[mt] + a_chunk[ks]));
                ldsm4(fAh[mt], sAh + so);
                ldsm4(fAl[mt], sAl + so);
            }
            uint32_t fBh[2][4], fBl[2][4];
#pragma unroll
            for (int nt2 = 0; nt2 < 2; nt2++) {
                uint32_t so = sw128((uint32_t)(b_row[nt2] + b_chunk[ks]));
                ldsm4(fBh[nt2], sBh + so);
                ldsm4(fBl[nt2], sBl + so);
            }
#pragma unroll
            for (int mt = 0; mt < 4; mt++) {
#pragma unroll
                for (int nt = 0; nt < 4; nt++) {
                    const int nt2 = nt >> 1, h = (nt & 1) * 2;
                    float* d = acc[mt][nt];
                    mma_tf32(d, fAh[mt], fBh[nt2][h], fBh[nt2][h + 1]);
                    mma_tf32(d, fAl[mt], fBh[nt2][h], fBh[nt2][h + 1]);
                    mma_tf32(d, fAh[mt], fBl[nt2][h], fBl[nt2][h + 1]);
                }
            }
        }
        __syncthreads();
    }

    // ---- epilogue
    const int rbase = m0 + wm * 64 + (lane >> 2);
    const int cbase = n0 + wn * 32 + (lane & 3) * 2;

#pragma unroll
    for (int mt = 0; mt < 4; mt++) {
#pragma unroll
        for (int nt = 0; nt < 4; nt++) {
            const float* d = acc[mt][nt];
            const int col = cbase + nt * 8;
            const long long r0 = rbase + mt * 16;
            const long long r1 = r0 + 8;
            float b0f = 0.0f, b1f = 0.0f;
            if (bias) { b0f = bias[col]; b1f = bias[col + 1]; }

            if (EPI == 0) {
                float* C = C0 + (long long)bz * sC;
                float2 v0 = make_float2(d[0] + b0f, d[1] + b1f);
                float2 v1 = make_float2(d[2] + b0f, d[3] + b1f);
                *reinterpret_cast<float2*>(&C[r0 * N + col]) = v0;
                *reinterpret_cast<float2*>(&C[r1 * N + col]) = v1;
            } else if (EPI == 1) {
                float* Ch = C0 + (long long)bz * sC;
                float* Cl = C1 + (long long)bz * sC;
                float v00 = d[0] + b0f, v01 = d[1] + b1f;
                float v10 = d[2] + b0f, v11 = d[3] + b1f;
                float h00 = f2tf32(v00), h01 = f2tf32(v01);
                float h10 = f2tf32(v10), h11 = f2tf32(v11);
                *reinterpret_cast<float2*>(&Ch[r0 * N + col]) =
                    make_float2(h00, h01);
                *reinterpret_cast<float2*>(&Ch[r1 * N + col]) =
                    make_float2(h10, h11);
                *reinterpret_cast<float2*>(&Cl[r0 * N + col]) =
                    make_float2(f2tf32(v00 - h00), f2tf32(v01 - h01));
                *reinterpret_cast<float2*>(&Cl[r1 * N + col]) =
                    make_float2(f2tf32(v10 - h10), f2tf32(v11 - h11));
            } else {  // EPI == 2: v^T split store, layout [b][n][t]
#pragma unroll
                for (int e = 0; e < 4; e++) {
                    const long long mr = (e < 2) ? r0 : r1;
                    const int n = col + (e & 1);
                    const float v = d[e] + ((e & 1) ? b1f : b0f);
                    const long long bb = mr >> 11;      // SEQ rows per batch
                    const long long t  = mr & 2047;
                    const float h = f2tf32(v);
                    const long long idx = (bb * DIMN + n) * SEQ + t;
                    C0[idx] = h;
                    C1[idx] = f2tf32(v - h);
                }
            }
        }
    }
}

// ----------------------------------------------------------------------------
// tf32 hi/lo split of external inputs (lo re-rounded to exact tf32)
// ----------------------------------------------------------------------------
__global__ void __launch_bounds__(256)
split_kernel(const float* __restrict__ src, float* __restrict__ hi,
             float* __restrict__ lo, int n4)
{
    const int i = blockIdx.x * 256 + threadIdx.x;
    if (i < n4) {
        float4 v = reinterpret_cast<const float4*>(src)[i];
        float4 h, l;
        h.x = f2tf32(v.x); l.x = f2tf32(v.x - h.x);
        h.y = f2tf32(v.y); l.y = f2tf32(v.y - h.y);
        h.z = f2tf32(v.z); l.z = f2tf32(v.z - h.z);
        h.w = f2tf32(v.w); l.w = f2tf32(v.w - h.w);
        reinterpret_cast<float4*>(hi)[i] = h;
        reinterpret_cast<float4*>(lo)[i] = l;
    }
}

// ----------------------------------------------------------------------------
// theta + softmax; emits split probabilities p = ph + pl
// theta = 0.5 + 0.2*sigmoid(x) + 0.15*tanh(x) + 0.1*relu(x)
// ----------------------------------------------------------------------------
__global__ void __launch_bounds__(256)
theta_softmax(const float* __restrict__ S, float* __restrict__ Ph,
              float* __restrict__ Pl)
{
    const long long ro = (long long)blockIdx.x * SEQ;
    const int tid  = threadIdx.x;
    const int lane = tid & 31;
    const int wid  = tid >> 5;
    __shared__ float red[8];

    float th[8];
    float mx = -1e30f;
#pragma unroll
    for (int j = 0; j < 8; j++) {
        float x = S[ro + tid + j * 256];
        float sg = 1.0f / (1.0f + __expf(-x));
        float t;
        asm("tanh.approx.f32 %0, %1;" : "=f"(t) : "f"(x));
        float v = 0.5f + 0.2f * sg + 0.15f * t + 0.1f * fmaxf(x, 0.0f);
        th[j] = v;
        mx = fmaxf(mx, v);
    }
#pragma unroll
    for (int o = 16; o > 0; o >>= 1)
        mx = fmaxf(mx, __shfl_xor_sync(0xFFFFFFFFu, mx, o));
    if (lane == 0) red[wid] = mx;
    __syncthreads();
    mx = red[0];
#pragma unroll
    for (int w = 1; w < 8; w++) mx = fmaxf(mx, red[w]);
    __syncthreads();

    float sum = 0.0f;
#pragma unroll
    for (int j = 0; j < 8; j++) {
        float e = __expf(th[j] - mx);
        th[j] = e;
        sum += e;
    }
#pragma unroll
    for (int o = 16; o > 0; o >>= 1)
        sum += __shfl_xor_sync(0xFFFFFFFFu, sum, o);
    if (lane == 0) red[wid] = sum;
    __syncthreads();
    sum = red[0];
#pragma unroll
    for (int w = 1; w < 8; w++) sum += red[w];

    const float inv = 1.0f / sum;
#pragma unroll
    for (int j = 0; j < 8; j++) {
        float p = th[j] * inv;
        float h = f2tf32(p);
        Ph[ro + tid + j * 256] = h;
        Pl[ro + tid + j * 256] = f2tf32(p - h);
    }
}

// ----------------------------------------------------------------------------
// launch — inputs: x, Wq, bq, Wk, bk, Wv, bv, Wo, bo
// ----------------------------------------------------------------------------
extern "C" void kernel_launch(void* const* d_in, const int* in_sizes, int n_in,
                              void* d_out, int out_size)
{
    const float* x  = (const float*)d_in[0];
    const float* Wq = (const float*)d_in[1];
    const float* bq = (const float*)d_in[2];
    const float* Wk = (const float*)d_in[3];
    const float* bk = (const float*)d_in[4];
    const float* Wv = (const float*)d_in[5];
    const float* bv = (const float*)d_in[6];
    const float* Wo = (const float*)d_in[7];
    const float* bo = (const float*)d_in[8];
    float* out = (float*)d_out;

    cudaFuncSetAttribute(gemm_x3<0>, cudaFuncAttributeMaxDynamicSharedMemorySize, SMEM_BYTES);
    cudaFuncSetAttribute(gemm_x3<1>, cudaFuncAttributeMaxDynamicSharedMemorySize, SMEM_BYTES);
    cudaFuncSetAttribute(gemm_x3<2>, cudaFuncAttributeMaxDynamicSharedMemorySize, SMEM_BYTES);

#define SYM(ptr, sym) void* ptr##_v; cudaGetSymbolAddress(&ptr##_v, sym); \
    float* ptr = (float*)ptr##_v
    SYM(xh, g_xh);  SYM(xl, g_xl);
    SYM(wh, g_wh);  SYM(wl, g_wl);
    SYM(qh, g_qh);  SYM(ql, g_ql);
    SYM(kh, g_kh);  SYM(kl, g_kl);
    SYM(vTh, g_vTh); SYM(vTl, g_vTl);
    SYM(sS, g_s);
    SYM(phh, g_ph); SYM(pll, g_pl);
    SYM(oh, g_oh);  SYM(ol, g_ol);
#undef SYM

    const int WSZ = DIMN * DIMN;
    float* Wqh = wh + 0 * WSZ; float* Wql = wl + 0 * WSZ;
    float* Wkh = wh + 1 * WSZ; float* Wkl = wl + 1 * WSZ;
    float* Wvh = wh + 2 * WSZ; float* Wvl = wl + 2 * WSZ;
    float* Woh = wh + 3 * WSZ; float* Wol = wl + 3 * WSZ;

    // splits of external inputs
    split_kernel<<<(MR * DIMN / 4 + 255) / 256, 256>>>(x,  xh,  xl,  MR * DIMN / 4);
    split_kernel<<<(WSZ / 4 + 255) / 256, 256>>>(Wq, Wqh, Wql, WSZ / 4);
    split_kernel<<<(WSZ / 4 + 255) / 256, 256>>>(Wk, Wkh, Wkl, WSZ / 4);
    split_kernel<<<(WSZ / 4 + 255) / 256, 256>>>(Wv, Wvh, Wvl, WSZ / 4);
    split_kernel<<<(WSZ / 4 + 255) / 256, 256>>>(Wo, Woh, Wol, WSZ / 4);

    const long long QS = (long long)SEQ * DIMN;  // q/k/v/o per-batch stride
    const long long SS = (long long)SEQ * SEQ;   // scores per-batch stride

    // projections (batch folded into M, strides 0)
    dim3 gp(DIMN / BN, MR / BM, 1);
    gemm_x3<1><<<gp, NTHREADS, SMEM_BYTES>>>(xh, xl, Wqh, Wql, bq, qh, ql,
                                             MR, DIMN, DIMN, 0, 0, 0);
    gemm_x3<1><<<gp, NTHREADS, SMEM_BYTES>>>(xh, xl, Wkh, Wkl, bk, kh, kl,
                                             MR, DIMN, DIMN, 0, 0, 0);
    gemm_x3<2><<<gp, NTHREADS, SMEM_BYTES>>>(xh, xl, Wvh, Wvl, bv, vTh, vTl,
                                             MR, DIMN, DIMN, 0, 0, 0);

    // scores S[b] = Q[b] @ K[b]^T
    dim3 gs(SEQ / BN, SEQ / BM, BATCH);
    gemm_x3<0><<<gs, NTHREADS, SMEM_BYTES>>>(qh, ql, kh, kl, nullptr, sS, nullptr,
                                             SEQ, SEQ, DIMN, QS, QS, SS);

    // theta + softmax -> split probabilities
    theta_softmax<<<BATCH * SEQ, 256>>>(sS, phh, pll);

    // O[b] = P[b] @ V[b]  (V stored transposed -> NT)
    dim3 gpv(DIMN / BN, SEQ / BM, BATCH);
    gemm_x3<1><<<gpv, NTHREADS, SMEM_BYTES>>>(phh, pll, vTh, vTl, nullptr, oh, ol,
                                              SEQ, DIMN, SEQ, SS,
                                              (long long)DIMN * SEQ, QS);

    // out = O @ Wo^T + bo
    gemm_x3<0><<<gp, NTHREADS, SMEM_BYTES>>>(oh, ol, Woh, Wol, bo, out, nullptr,
                                             MR, DIMN, DIMN, 0, 0, 0);
}

// round 4
// speedup vs baseline: 1.8358x; 1.0641x over previous
#include <cuda_runtime.h>
#include <cstdint>

// ---------------- problem constants ----------------
#define SEQ    2048
#define DIMN   1024
#define BATCH  2
#define MR     4096            // BATCH*SEQ

// ---------------- GEMM tiling ----------------
#define BM 128
#define BN 128
#define BK 32
#define NTHREADS 256

#define TILEB  (BM * BK * 4)           // 16384 B per operand tile
#define STAGE  (4 * TILEB)             // Ah, Al, Bh, Bl slots = 65536 B
#define NSTAGE 3
#define SMEM_BYTES (NSTAGE * STAGE)    // 196608 B

// ---------------- scratch (__device__ globals; no allocs allowed) ----------------
static __device__ float g_xh[MR * DIMN],  g_xl[MR * DIMN];
static __device__ float g_wh[4][DIMN * DIMN], g_wl[4][DIMN * DIMN]; // q,k,v,o
static __device__ float g_qh[MR * DIMN],  g_ql[MR * DIMN];
static __device__ float g_kh[MR * DIMN],  g_kl[MR * DIMN];
static __device__ float g_vTh[MR * DIMN], g_vTl[MR * DIMN];         // [B][D][S]
static __device__ float g_s[BATCH * SEQ * SEQ];
static __device__ float g_p[BATCH * SEQ * SEQ];                     // tf32-rounded P
static __device__ float g_o[MR * DIMN];                             // tf32-rounded O

// ---------------- helpers ----------------
__device__ __forceinline__ uint32_t smem_u32(const void* p) {
    uint32_t a;
    asm("{ .reg .u64 t; cvta.to.shared.u64 t, %1; cvt.u32.u64 %0, t; }"
        : "=r"(a) : "l"(p));
    return a;
}

__device__ __forceinline__ float f2tf32(float x) {
    uint32_t u;
    asm("cvt.rna.tf32.f32 %0, %1;" : "=r"(u) : "f"(x));
    return __uint_as_float(u);
}

__device__ __forceinline__ void cp16(uint32_t saddr, const float* g) {
    asm volatile("cp.async.cg.shared.global [%0], [%1], 16;"
                 :: "r"(saddr), "l"(g) : "memory");
}

__device__ __forceinline__ void ldsm4(uint32_t* r, uint32_t addr) {
    asm volatile("ldmatrix.sync.aligned.m8n8.x4.shared.b16 {%0,%1,%2,%3}, [%4];"
                 : "=r"(r[0]), "=r"(r[1]), "=r"(r[2]), "=r"(r[3])
                 : "r"(addr));
}

__device__ __forceinline__ void mma_tf32(float* d, const uint32_t* a,
                                         uint32_t b0, uint32_t b1) {
    asm volatile(
        "mma.sync.aligned.m16n8k8.row.col.f32.tf32.tf32.f32 "
        "{%0,%1,%2,%3}, {%4,%5,%6,%7}, {%8,%9}, {%0,%1,%2,%3};"
        : "+f"(d[0]), "+f"(d[1]), "+f"(d[2]), "+f"(d[3])
        : "r"(a[0]), "r"(a[1]), "r"(a[2]), "r"(a[3]), "r"(b0), "r"(b1));
}

__device__ __forceinline__ uint32_t sw128(uint32_t x) {
    return x ^ ((x >> 3) & 0x70);   // 128B-row xor swizzle
}

// ----------------------------------------------------------------------------
// Multi-pass tf32 GEMM via mma.sync:  C[M,N] = A[M,K] @ B[N,K]^T
// NPASS = 3: A = Ah+Al, B = Bh+Bl, terms hh + lh + hl (tf32x3 ~ fp32)
// NPASS = 2: A = Ah only,          terms hh + hl      (A-lo dropped)
// EPI: 0 = plain fp32 store (+optional bias)        (QK scores, final output)
//      1 = split store hi/lo (+optional bias)       (q/k projections)
//      2 = split store TRANSPOSED [b][n][t] (+bias) (v projection -> v^T)
//      3 = tf32-rounded single store                (PV -> O)
// ----------------------------------------------------------------------------
template <int NPASS, int EPI>
__global__ void __launch_bounds__(NTHREADS, 1)
gemm_mp(const float* __restrict__ Ah, const float* __restrict__ Al,
        const float* __restrict__ Bh, const float* __restrict__ Bl,
        const float* __restrict__ bias,
        float* __restrict__ C0, float* __restrict__ C1,
        int M, int N, int K,
        long long sA, long long sB, long long sC)
{
    extern __shared__ char dsmem[];
    const uint32_t sbase = smem_u32(dsmem);

    const int tid  = threadIdx.x;
    const int lane = tid & 31;
    const int wid  = tid >> 5;
    const int wm   = wid >> 2;        // 0..1 (m warp row)
    const int wn   = wid & 3;         // 0..3 (n warp col)

    const int m0 = blockIdx.y * BM;
    const int n0 = blockIdx.x * BN;
    const int bz = blockIdx.z;

    const float* pAh = Ah + (long long)bz * sA;
    const float* pAl = Al + (long long)bz * sA;
    const float* pBh = Bh + (long long)bz * sB;
    const float* pBl = Bl + (long long)bz * sB;

    // ---- cp.async slots: each thread copies 4 x 16B chunks per operand tile
    uint32_t g_sw[4];
    int      a_off[4];
    int      b_off[4];
#pragma unroll
    for (int i = 0; i < 4; i++) {
        int c   = tid + i * NTHREADS;        // 0..1023
        int row = c >> 3;                    // 0..127
        int ch  = c & 7;                     // 16B chunk in 128B row
        g_sw[i]  = sw128((uint32_t)(row * 128 + ch * 16));
        a_off[i] = (m0 + row) * K + ch * 4;
        b_off[i] = (n0 + row) * K + ch * 4;
    }

    auto load_tile = [&](int kt, int s) {
        const int k0 = kt * BK;
        const uint32_t st = sbase + (uint32_t)s * STAGE;
#pragma unroll
        for (int i = 0; i < 4; i++) {
            cp16(st + g_sw[i],                 pAh + a_off[i] + k0);
            if (NPASS == 3)
                cp16(st + TILEB + g_sw[i],     pAl + a_off[i] + k0);
            cp16(st + 2 * TILEB + g_sw[i],     pBh + b_off[i] + k0);
            cp16(st + 3 * TILEB + g_sw[i],     pBl + b_off[i] + k0);
        }
        asm volatile("cp.async.commit_group;" ::: "memory");
    };

    // ---- ldmatrix address components
    const int piece = lane >> 3;
    const int pr    = lane & 7;

    int a_row[4], a_chunk[4];
#pragma unroll
    for (int mt = 0; mt < 4; mt++)
        a_row[mt] = (wm * 64 + mt * 16 + ((piece & 1) << 3) + pr) * 128;
#pragma unroll
    for (int ks = 0; ks < 4; ks++)
        a_chunk[ks] = (ks * 2 + (piece >> 1)) * 16;

    int b_row[2], b_chunk[4];
#pragma unroll
    for (int nt2 = 0; nt2 < 2; nt2++)
        b_row[nt2] = (wn * 32 + nt2 * 16 + ((piece >> 1) << 3) + pr) * 128;
#pragma unroll
    for (int ks = 0; ks < 4; ks++)
        b_chunk[ks] = (ks * 2 + (piece & 1)) * 16;

    float acc[4][4][4];
#pragma unroll
    for (int i = 0; i < 4; i++)
#pragma unroll
        for (int j = 0; j < 4; j++)
#pragma unroll
            for (int r = 0; r < 4; r++) acc[i][j][r] = 0.0f;

    const int KT = K / BK;
    load_tile(0, 0);
    if (KT > 1) load_tile(1, 1);

    for (int kt = 0; kt < KT; kt++) {
        const int s = kt % NSTAGE;
        // wait until group kt is complete (1 newer group may stay in flight)
        if (kt + 1 < KT)
            asm volatile("cp.async.wait_group 1;" ::: "memory");
        else
            asm volatile("cp.async.wait_group 0;" ::: "memory");
        __syncthreads();   // also guards stage (kt+2)%3 against lagging readers
        if (kt + 2 < KT) load_tile(kt + 2, (kt + 2) % NSTAGE);

        const uint32_t sAh = sbase + (uint32_t)s * STAGE;
        const uint32_t sAl = sAh + TILEB;
        const uint32_t sBh = sAh + 2 * TILEB;
        const uint32_t sBl = sAh + 3 * TILEB;

#pragma unroll
        for (int ks = 0; ks < 4; ks++) {
            uint32_t fAh[4][4], fAl[4][4];
#pragma unroll
            for (int mt = 0; mt < 4; mt++) {
                uint32_t so = sw128((uint32_t)(a_row[mt] + a_chunk[ks]));
                ldsm4(fAh[mt], sAh + so);
                if (NPASS == 3) ldsm4(fAl[mt], sAl + so);
            }
            uint32_t fBh[2][4], fBl[2][4];
#pragma unroll
            for (int nt2 = 0; nt2 < 2; nt2++) {
                uint32_t so = sw128((uint32_t)(b_row[nt2] + b_chunk[ks]));
                ldsm4(fBh[nt2], sBh + so);
                ldsm4(fBl[nt2], sBl + so);
            }
#pragma unroll
            for (int mt = 0; mt < 4; mt++) {
#pragma unroll
                for (int nt = 0; nt < 4; nt++) {
                    const int nt2 = nt >> 1, h = (nt & 1) * 2;
                    float* d = acc[mt][nt];
                    mma_tf32(d, fAh[mt], fBh[nt2][h], fBh[nt2][h + 1]);
                    if (NPASS == 3)
                        mma_tf32(d, fAl[mt], fBh[nt2][h], fBh[nt2][h + 1]);
                    mma_tf32(d, fAh[mt], fBl[nt2][h], fBl[nt2][h + 1]);
                }
            }
        }
    }

    // ---- epilogue
    const int rbase = m0 + wm * 64 + (lane >> 2);
    const int cbase = n0 + wn * 32 + (lane & 3) * 2;

#pragma unroll
    for (int mt = 0; mt < 4; mt++) {
#pragma unroll
        for (int nt = 0; nt < 4; nt++) {
            const float* d = acc[mt][nt];
            const int col = cbase + nt * 8;
            const long long r0 = rbase + mt * 16;
            const long long r1 = r0 + 8;
            float b0f = 0.0f, b1f = 0.0f;
            if (bias) { b0f = bias[col]; b1f = bias[col + 1]; }

            if (EPI == 0) {
                float* C = C0 + (long long)bz * sC;
                *reinterpret_cast<float2*>(&C[r0 * N + col]) =
                    make_float2(d[0] + b0f, d[1] + b1f);
                *reinterpret_cast<float2*>(&C[r1 * N + col]) =
                    make_float2(d[2] + b0f, d[3] + b1f);
            } else if (EPI == 1) {
                float* Ch = C0 + (long long)bz * sC;
                float* Cl = C1 + (long long)bz * sC;
                float v00 = d[0] + b0f, v01 = d[1] + b1f;
                float v10 = d[2] + b0f, v11 = d[3] + b1f;
                float h00 = f2tf32(v00), h01 = f2tf32(v01);
                float h10 = f2tf32(v10), h11 = f2tf32(v11);
                *reinterpret_cast<float2*>(&Ch[r0 * N + col]) =
                    make_float2(h00, h01);
                *reinterpret_cast<float2*>(&Ch[r1 * N + col]) =
                    make_float2(h10, h11);
                *reinterpret_cast<float2*>(&Cl[r0 * N + col]) =
                    make_float2(f2tf32(v00 - h00), f2tf32(v01 - h01));
                *reinterpret_cast<float2*>(&Cl[r1 * N + col]) =
                    make_float2(f2tf32(v10 - h10), f2tf32(v11 - h11));
            } else if (EPI == 2) {  // v^T split store, layout [b][n][t]
#pragma unroll
                for (int e = 0; e < 4; e++) {
                    const long long mr = (e < 2) ? r0 : r1;
                    const int n = col + (e & 1);
                    const float v = d[e] + ((e & 1) ? b1f : b0f);
                    const long long bb = mr >> 11;      // SEQ rows per batch
                    const long long t  = mr & 2047;
                    const float h = f2tf32(v);
                    const long long idx = (bb * DIMN + n) * SEQ + t;
                    C0[idx] = h;
                    C1[idx] = f2tf32(v - h);
                }
            } else {  // EPI == 3: tf32-rounded single store
                float* C = C0 + (long long)bz * sC;
                *reinterpret_cast<float2*>(&C[r0 * N + col]) =
                    make_float2(f2tf32(d[0] + b0f), f2tf32(d[1] + b1f));
                *reinterpret_cast<float2*>(&C[r1 * N + col]) =
                    make_float2(f2tf32(d[2] + b0f), f2tf32(d[3] + b1f));
            }
        }
    }
}

// ----------------------------------------------------------------------------
// tf32 hi/lo split of external inputs (lo re-rounded to exact tf32)
// ----------------------------------------------------------------------------
__global__ void __launch_bounds__(256)
split_kernel(const float* __restrict__ src, float* __restrict__ hi,
             float* __restrict__ lo, int n4)
{
    const int i = blockIdx.x * 256 + threadIdx.x;
    if (i < n4) {
        float4 v = reinterpret_cast<const float4*>(src)[i];
        float4 h, l;
        h.x = f2tf32(v.x); l.x = f2tf32(v.x - h.x);
        h.y = f2tf32(v.y); l.y = f2tf32(v.y - h.y);
        h.z = f2tf32(v.z); l.z = f2tf32(v.z - h.z);
        h.w = f2tf32(v.w); l.w = f2tf32(v.w - h.w);
        reinterpret_cast<float4*>(hi)[i] = h;
        reinterpret_cast<float4*>(lo)[i] = l;
    }
}

// ----------------------------------------------------------------------------
// theta + softmax; emits tf32-rounded probabilities (lo dropped; PV is x2)
// theta = 0.5 + 0.2*sigmoid(x) + 0.15*tanh(x) + 0.1*relu(x)
// ----------------------------------------------------------------------------
__global__ void __launch_bounds__(256)
theta_softmax(const float* __restrict__ S, float* __restrict__ P)
{
    const long long ro = (long long)blockIdx.x * SEQ;
    const int tid  = threadIdx.x;
    const int lane = tid & 31;
    const int wid  = tid >> 5;
    __shared__ float red[8];

    float th[8];
    float mx = -1e30f;
#pragma unroll
    for (int j = 0; j < 8; j++) {
        float x = S[ro + tid + j * 256];
        float sg = 1.0f / (1.0f + __expf(-x));
        float t;
        asm("tanh.approx.f32 %0, %1;" : "=f"(t) : "f"(x));
        float v = 0.5f + 0.2f * sg + 0.15f * t + 0.1f * fmaxf(x, 0.0f);
        th[j] = v;
        mx = fmaxf(mx, v);
    }
#pragma unroll
    for (int o = 16; o > 0; o >>= 1)
        mx = fmaxf(mx, __shfl_xor_sync(0xFFFFFFFFu, mx, o));
    if (lane == 0) red[wid] = mx;
    __syncthreads();
    mx = red[0];
#pragma unroll
    for (int w = 1; w < 8; w++) mx = fmaxf(mx, red[w]);
    __syncthreads();

    float sum = 0.0f;
#pragma unroll
    for (int j = 0; j < 8; j++) {
        float e = __expf(th[j] - mx);
        th[j] = e;
        sum += e;
    }
#pragma unroll
    for (int o = 16; o > 0; o >>= 1)
        sum += __shfl_xor_sync(0xFFFFFFFFu, sum, o);
    if (lane == 0) red[wid] = sum;
    __syncthreads();
    sum = red[0];
#pragma unroll
    for (int w = 1; w < 8; w++) sum += red[w];

    const float inv = 1.0f / sum;
#pragma unroll
    for (int j = 0; j < 8; j++)
        P[ro + tid + j * 256] = f2tf32(th[j] * inv);
}

// ----------------------------------------------------------------------------
// launch — inputs: x, Wq, bq, Wk, bk, Wv, bv, Wo, bo
// ----------------------------------------------------------------------------
extern "C" void kernel_launch(void* const* d_in, const int* in_sizes, int n_in,
                              void* d_out, int out_size)
{
    const float* x  = (const float*)d_in[0];
    const float* Wq = (const float*)d_in[1];
    const float* bq = (const float*)d_in[2];
    const float* Wk = (const float*)d_in[3];
    const float* bk = (const float*)d_in[4];
    const float* Wv = (const float*)d_in[5];
    const float* bv = (const float*)d_in[6];
    const float* Wo = (const float*)d_in[7];
    const float* bo = (const float*)d_in[8];
    float* out = (float*)d_out;

    cudaFuncSetAttribute(gemm_mp<3, 0>, cudaFuncAttributeMaxDynamicSharedMemorySize, SMEM_BYTES);
    cudaFuncSetAttribute(gemm_mp<3, 1>, cudaFuncAttributeMaxDynamicSharedMemorySize, SMEM_BYTES);
    cudaFuncSetAttribute(gemm_mp<3, 2>, cudaFuncAttributeMaxDynamicSharedMemorySize, SMEM_BYTES);
    cudaFuncSetAttribute(gemm_mp<2, 3>, cudaFuncAttributeMaxDynamicSharedMemorySize, SMEM_BYTES);
    cudaFuncSetAttribute(gemm_mp<2, 0>, cudaFuncAttributeMaxDynamicSharedMemorySize, SMEM_BYTES);

#define SYM(ptr, sym) void* ptr##_v; cudaGetSymbolAddress(&ptr##_v, sym); \
    float* ptr = (float*)ptr##_v
    SYM(xh, g_xh);  SYM(xl, g_xl);
    SYM(wh, g_wh);  SYM(wl, g_wl);
    SYM(qh, g_qh);  SYM(ql, g_ql);
    SYM(kh, g_kh);  SYM(kl, g_kl);
    SYM(vTh, g_vTh); SYM(vTl, g_vTl);
    SYM(sS, g_s);
    SYM(pP, g_p);
    SYM(oO, g_o);
#undef SYM

    const int WSZ = DIMN * DIMN;
    float* Wqh = wh + 0 * WSZ; float* Wql = wl + 0 * WSZ;
    float* Wkh = wh + 1 * WSZ; float* Wkl = wl + 1 * WSZ;
    float* Wvh = wh + 2 * WSZ; float* Wvl = wl + 2 * WSZ;
    float* Woh = wh + 3 * WSZ; float* Wol = wl + 3 * WSZ;

    // splits of external inputs
    split_kernel<<<(MR * DIMN / 4 + 255) / 256, 256>>>(x,  xh,  xl,  MR * DIMN / 4);
    split_kernel<<<(WSZ / 4 + 255) / 256, 256>>>(Wq, Wqh, Wql, WSZ / 4);
    split_kernel<<<(WSZ / 4 + 255) / 256, 256>>>(Wk, Wkh, Wkl, WSZ / 4);
    split_kernel<<<(WSZ / 4 + 255) / 256, 256>>>(Wv, Wvh, Wvl, WSZ / 4);
    split_kernel<<<(WSZ / 4 + 255) / 256, 256>>>(Wo, Woh, Wol, WSZ / 4);

    const long long QS = (long long)SEQ * DIMN;  // q/k/v/o per-batch stride
    const long long SS = (long long)SEQ * SEQ;   // scores per-batch stride

    // projections (batch folded into M, strides 0): x3, accurate
    dim3 gp(DIMN / BN, MR / BM, 1);
    gemm_mp<3, 1><<<gp, NTHREADS, SMEM_BYTES>>>(xh, xl, Wqh, Wql, bq, qh, ql,
                                                MR, DIMN, DIMN, 0, 0, 0);
    gemm_mp<3, 1><<<gp, NTHREADS, SMEM_BYTES>>>(xh, xl, Wkh, Wkl, bk, kh, kl,
                                                MR, DIMN, DIMN, 0, 0, 0);
    gemm_mp<3, 2><<<gp, NTHREADS, SMEM_BYTES>>>(xh, xl, Wvh, Wvl, bv, vTh, vTl,
                                                MR, DIMN, DIMN, 0, 0, 0);

    // scores S[b] = Q[b] @ K[b]^T : x3 (error amplified via 0.1*relu)
    dim3 gs(SEQ / BN, SEQ / BM, BATCH);
    gemm_mp<3, 0><<<gs, NTHREADS, SMEM_BYTES>>>(qh, ql, kh, kl, nullptr, sS, nullptr,
                                                SEQ, SEQ, DIMN, QS, QS, SS);

    // theta + softmax -> tf32-rounded P
    theta_softmax<<<BATCH * SEQ, 256>>>(sS, pP);

    // O[b] = P[b] @ V[b] : x2 (P_hi*(V_hi+V_lo)), tf32-rounded O out
    dim3 gpv(DIMN / BN, SEQ / BM, BATCH);
    gemm_mp<2, 3><<<gpv, NTHREADS, SMEM_BYTES>>>(pP, pP, vTh, vTl, nullptr, oO, nullptr,
                                                 SEQ, DIMN, SEQ, SS,
                                                 (long long)DIMN * SEQ, QS);

    // out = O @ Wo^T + bo : x2 (O_hi*(W_hi+W_lo))
    gemm_mp<2, 0><<<gp, NTHREADS, SMEM_BYTES>>>(oO, oO, Woh, Wol, bo, out, nullptr,
                                                MR, DIMN, DIMN, 0, 0, 0);
}